// round 5
// baseline (speedup 1.0000x reference)
#include <cuda_runtime.h>
#include <cuda_bf16.h>

// SSIM loss, fully fused. (1,3,2048,2048) fp32, VALID 11-tap separable Gaussian
// (sigma=1.5). Output scalar fp32 = 1 - mean(ssim_map) over (3,2038,2038).
//
// v5 = v2 geometry (32x32 tile, 128 threads, strides 43/33) with:
//  - packed f32x2 FMAs in both conv phases (half the FMA issue slots)
//  - deterministic fixed-point ull atomic reduction (proven -9us tail)

#define H_DIM 2048
#define W_DIM 2048
#define OUT_DIM 2038
#define TILE 32
#define IN_TILE 42
#define NTHREADS 128
#define GRID_X 64
#define GRID_Y 64

// Normalized gaussian(sigma=1.5, size=11); sum == 1.0f. Symmetric: W[t]=W[10-t].
#define W0 0.00102841f
#define W1 0.00759878f
#define W2 0.03600077f
#define W3 0.10936067f
#define W4 0.21300553f
#define W5 0.26601168f

#define FIXED_SCALE 16777216.0   // 2^24

typedef unsigned long long u64;

__device__ unsigned long long g_accum = 0ull;

__device__ __forceinline__ u64 pk2(float lo, float hi) {
    u64 r;
    asm("mov.b64 %0, {%1, %2};" : "=l"(r) : "f"(lo), "f"(hi));
    return r;
}
__device__ __forceinline__ void unpk2(u64 v, float& lo, float& hi) {
    asm("mov.b64 {%0, %1}, %2;" : "=f"(lo), "=f"(hi) : "l"(v));
}
__device__ __forceinline__ u64 mul2(u64 a, u64 b) {
    u64 d;
    asm("mul.rn.f32x2 %0, %1, %2;" : "=l"(d) : "l"(a), "l"(b));
    return d;
}
__device__ __forceinline__ u64 fma2(u64 a, u64 b, u64 c) {
    u64 d;
    asm("fma.rn.f32x2 %0, %1, %2, %3;" : "=l"(d) : "l"(a), "l"(b), "l"(c));
    return d;
}

// 8 outputs of an 11-tap conv over v[18], computed as 4 f32x2 pairs.
// Wp[6] = packed symmetric weights. Bit-identical to the scalar version.
__device__ __forceinline__ void conv11_x2(const float* __restrict__ v,
                                          float* __restrict__ out,
                                          const u64* __restrict__ Wp) {
    u64 pe[9], po[8];
    #pragma unroll
    for (int k = 0; k < 9; ++k) pe[k] = pk2(v[2 * k], v[2 * k + 1]);
    #pragma unroll
    for (int k = 0; k < 8; ++k) po[k] = pk2(v[2 * k + 1], v[2 * k + 2]);
    #pragma unroll
    for (int q = 0; q < 4; ++q) {
        u64 a = mul2(Wp[0], pe[q]);                       // t = 0
        #pragma unroll
        for (int t = 1; t <= 10; ++t) {
            int wi = (t < 6) ? t : 10 - t;                // symmetric weights
            u64 src = (t & 1) ? po[q + (t >> 1)] : pe[q + (t >> 1)];
            a = fma2(Wp[wi], src, a);
        }
        unpk2(a, out[2 * q], out[2 * q + 1]);
    }
}

__global__ __launch_bounds__(NTHREADS)
void ssim_main_kernel(const float* __restrict__ xin, const float* __restrict__ yin) {
    __shared__ float sx[IN_TILE][43];    // conflict-free window loads
    __shared__ float sy[IN_TILE][43];
    __shared__ float hb[5][IN_TILE][33]; // conflict-free stores + vertical reads
    __shared__ float red[4];

    const int tid = threadIdx.x;
    const int gx0 = blockIdx.x * TILE;
    const int gy0 = blockIdx.y * TILE;
    const float* __restrict__ xp = xin + (size_t)blockIdx.z * (H_DIM * W_DIM);
    const float* __restrict__ yp = yin + (size_t)blockIdx.z * (H_DIM * W_DIM);

    u64 Wp[6];
    Wp[0] = pk2(W0, W0); Wp[1] = pk2(W1, W1); Wp[2] = pk2(W2, W2);
    Wp[3] = pk2(W3, W3); Wp[4] = pk2(W4, W4); Wp[5] = pk2(W5, W5);

    // ---- Load 42x42 x,y tile (zero clamp at image edge) ----
    for (int i = tid; i < IN_TILE * IN_TILE; i += NTHREADS) {
        int r = i / IN_TILE;
        int c = i - r * IN_TILE;
        int gr = gy0 + r;
        int gc = gx0 + c;
        float xv = 0.0f, yv = 0.0f;
        if (gr < H_DIM && gc < W_DIM) {
            int idx = gr * W_DIM + gc;
            xv = __ldg(xp + idx);
            yv = __ldg(yp + idx);
        }
        sx[r][c] = xv;
        sy[r][c] = yv;
    }
    __syncthreads();

    // ---- Phase A: horizontal blur of 5 maps; 42 rows x 4 runs of 8 = 168 tasks ----
    for (int task = tid; task < IN_TILE * 4; task += NTHREADS) {
        int r  = task >> 2;
        int c0 = (task & 3) << 3;
        float xw[18], yw[18], pw[18], acc[8];

        #pragma unroll
        for (int k = 0; k < 18; ++k) xw[k] = sx[r][c0 + k];
        conv11_x2(xw, acc, Wp);
        #pragma unroll
        for (int j = 0; j < 8; ++j) hb[0][r][c0 + j] = acc[j];

        #pragma unroll
        for (int k = 0; k < 18; ++k) yw[k] = sy[r][c0 + k];
        conv11_x2(yw, acc, Wp);
        #pragma unroll
        for (int j = 0; j < 8; ++j) hb[1][r][c0 + j] = acc[j];

        #pragma unroll
        for (int k = 0; k < 18; ++k) pw[k] = xw[k] * xw[k];
        conv11_x2(pw, acc, Wp);
        #pragma unroll
        for (int j = 0; j < 8; ++j) hb[2][r][c0 + j] = acc[j];

        #pragma unroll
        for (int k = 0; k < 18; ++k) pw[k] = yw[k] * yw[k];
        conv11_x2(pw, acc, Wp);
        #pragma unroll
        for (int j = 0; j < 8; ++j) hb[3][r][c0 + j] = acc[j];

        #pragma unroll
        for (int k = 0; k < 18; ++k) pw[k] = xw[k] * yw[k];
        conv11_x2(pw, acc, Wp);
        #pragma unroll
        for (int j = 0; j < 8; ++j) hb[4][r][c0 + j] = acc[j];
    }
    __syncthreads();

    // ---- Phase B: vertical blur (8 rows/thread, 4 warps) + SSIM + reduce ----
    const int tx  = tid & 31;            // output column
    const int tg  = tid >> 5;            // warp id: rows [tg*8, tg*8+8)
    const int oyb = tg << 3;

    float acc[5][8];
    #pragma unroll
    for (int m = 0; m < 5; ++m) {
        float v[18];
        #pragma unroll
        for (int k = 0; k < 18; ++k) v[k] = hb[m][oyb + k][tx];
        conv11_x2(v, acc[m], Wp);
    }

    const float C1 = 0.01f * 0.01f;
    const float C2 = 0.03f * 0.03f;
    float lsum = 0.0f;
    const int ox = gx0 + tx;
    #pragma unroll
    for (int j = 0; j < 8; ++j) {
        int oy = gy0 + oyb + j;
        if (oy < OUT_DIM && ox < OUT_DIM) {
            float mu1 = acc[0][j], mu2 = acc[1][j];
            float m11 = mu1 * mu1;
            float m22 = mu2 * mu2;
            float m12 = mu1 * mu2;
            float s1  = acc[2][j] - m11;
            float s2  = acc[3][j] - m22;
            float s12 = acc[4][j] - m12;
            float num = (2.0f * m12 + C1) * (2.0f * s12 + C2);
            float den = (m11 + m22 + C1) * (s1 + s2 + C2);
            lsum += __fdividef(num, den);
        }
    }

    #pragma unroll
    for (int off = 16; off > 0; off >>= 1)
        lsum += __shfl_down_sync(0xffffffffu, lsum, off);
    if (tx == 0) red[tg] = lsum;
    __syncthreads();
    if (tid == 0) {
        float bs = red[0] + red[1] + red[2] + red[3];
        u64 q = (u64)__double2ll_rn((double)bs * FIXED_SCALE);
        atomicAdd(&g_accum, q);   // integer adds commute: replay-deterministic
    }
}

__global__ void ssim_final_kernel(float* __restrict__ out) {
    unsigned long long v = g_accum;
    g_accum = 0ull;   // reset for next graph replay
    double mean = ((double)v / FIXED_SCALE) / (3.0 * (double)OUT_DIM * (double)OUT_DIM);
    out[0] = 1.0f - (float)mean;
}

extern "C" void kernel_launch(void* const* d_in, const int* in_sizes, int n_in,
                              void* d_out, int out_size) {
    const float* pred = (const float*)d_in[0];
    const float* targ = (const float*)d_in[1];
    float* out = (float*)d_out;

    dim3 grid(GRID_X, GRID_Y, 3);
    ssim_main_kernel<<<grid, NTHREADS>>>(pred, targ);
    ssim_final_kernel<<<1, 1>>>(out);
}